// round 3
// baseline (speedup 1.0000x reference)
#include <cuda_runtime.h>
#include <math.h>

#define NB    2048
#define NBITS 64
#define NH    512
#define NHV   256
#define STR   516   // padded row stride for h1s (bank spread, 16B-aligned)

// Scratch (device globals: no allocation allowed in kernel_launch)
__device__ float g_sp[NB * NH];    // shift_part = shift_soft @ ix_w1[64:]
__device__ float g_vs[NB * NHV];   // v_shift    = shift_soft @ v_w1[64:]

// ---------------------------------------------------------------------------
// Kernel 1: shift MLP + softmax + shift_part/v_shift projections.
// One block handles 8 batch rows; 256 threads.
// ---------------------------------------------------------------------------
__global__ __launch_bounds__(256) void shift_net_kernel(
    const float* __restrict__ shift_bits,
    const float* __restrict__ sd_w1, const float* __restrict__ sd_b1,
    const float* __restrict__ sd_w2, const float* __restrict__ sd_b2,
    const float* __restrict__ sd_w3, const float* __restrict__ sd_b3,
    const float* __restrict__ ix_w1, const float* __restrict__ v_w1)
{
    const int ROWS = 8;
    __shared__ float xs[ROWS][NBITS];
    __shared__ float hs[ROWS][NH];
    __shared__ float gs[ROWS][NH];
    __shared__ float lgs[ROWS][NBITS];
    __shared__ float sms[ROWS][NBITS];

    const int t  = threadIdx.x;
    const int b0 = blockIdx.x * ROWS;

    for (int idx = t; idx < ROWS * NBITS; idx += 256) {
        int r = idx >> 6, k = idx & 63;
        xs[r][k] = shift_bits[(b0 + r) * NBITS + k];
    }
    __syncthreads();

    // layer 1: hs = relu(xs @ sd_w1 + b1)   (K=64 -> 512 out)
    {
        const int j0 = t, j1 = t + 256;
        float a0[ROWS], a1[ROWS];
        #pragma unroll
        for (int r = 0; r < ROWS; r++) { a0[r] = 0.f; a1[r] = 0.f; }
        for (int k = 0; k < NBITS; k++) {
            float w0 = sd_w1[k * NH + j0];
            float w1 = sd_w1[k * NH + j1];
            #pragma unroll
            for (int r = 0; r < ROWS; r++) {
                a0[r] = fmaf(xs[r][k], w0, a0[r]);
                a1[r] = fmaf(xs[r][k], w1, a1[r]);
            }
        }
        float bb0 = sd_b1[j0], bb1 = sd_b1[j1];
        #pragma unroll
        for (int r = 0; r < ROWS; r++) {
            hs[r][j0] = fmaxf(a0[r] + bb0, 0.f);
            hs[r][j1] = fmaxf(a1[r] + bb1, 0.f);
        }
    }
    __syncthreads();

    // layer 2: gs = relu(hs @ sd_w2 + b2)   (K=512 -> 512 out)
    {
        const int j0 = t, j1 = t + 256;
        float a0[ROWS], a1[ROWS];
        #pragma unroll
        for (int r = 0; r < ROWS; r++) { a0[r] = 0.f; a1[r] = 0.f; }
        for (int k = 0; k < NH; k++) {
            float w0 = sd_w2[k * NH + j0];
            float w1 = sd_w2[k * NH + j1];
            #pragma unroll
            for (int r = 0; r < ROWS; r++) {
                a0[r] = fmaf(hs[r][k], w0, a0[r]);
                a1[r] = fmaf(hs[r][k], w1, a1[r]);
            }
        }
        float bb0 = sd_b2[j0], bb1 = sd_b2[j1];
        #pragma unroll
        for (int r = 0; r < ROWS; r++) {
            gs[r][j0] = fmaxf(a0[r] + bb0, 0.f);
            gs[r][j1] = fmaxf(a1[r] + bb1, 0.f);
        }
    }
    __syncthreads();

    // layer 3: logits = gs @ sd_w3 + b3   (512 -> 64)
    #pragma unroll
    for (int p = 0; p < 2; p++) {
        int idx = t + p * 256;        // 0..511
        int r = idx >> 6, j = idx & 63;
        float acc = 0.f;
        for (int k = 0; k < NH; k++)
            acc = fmaf(gs[r][k], sd_w3[k * NBITS + j], acc);
        lgs[r][j] = acc + sd_b3[j];
    }
    __syncthreads();

    // softmax over 64, warp w -> row w
    {
        int w = t >> 5, l = t & 31;
        float v0 = lgs[w][l], v1 = lgs[w][l + 32];
        float m = fmaxf(v0, v1);
        #pragma unroll
        for (int o = 16; o > 0; o >>= 1) m = fmaxf(m, __shfl_xor_sync(0xffffffffu, m, o));
        float e0 = expf(v0 - m), e1 = expf(v1 - m);
        float s = e0 + e1;
        #pragma unroll
        for (int o = 16; o > 0; o >>= 1) s += __shfl_xor_sync(0xffffffffu, s, o);
        float inv = 1.f / s;
        sms[w][l] = e0 * inv;
        sms[w][l + 32] = e1 * inv;
    }
    __syncthreads();

    // shift_part = soft @ ix_w1[64:128]   (-> [rows, 512])
    {
        const int j0 = t, j1 = t + 256;
        float a0[ROWS], a1[ROWS];
        #pragma unroll
        for (int r = 0; r < ROWS; r++) { a0[r] = 0.f; a1[r] = 0.f; }
        for (int k = 0; k < NBITS; k++) {
            float w0 = ix_w1[(NBITS + k) * NH + j0];
            float w1 = ix_w1[(NBITS + k) * NH + j1];
            #pragma unroll
            for (int r = 0; r < ROWS; r++) {
                a0[r] = fmaf(sms[r][k], w0, a0[r]);
                a1[r] = fmaf(sms[r][k], w1, a1[r]);
            }
        }
        #pragma unroll
        for (int r = 0; r < ROWS; r++) {
            g_sp[(b0 + r) * NH + j0] = a0[r];
            g_sp[(b0 + r) * NH + j1] = a1[r];
        }
    }

    // v_shift = soft @ v_w1[64:128]   (-> [rows, 256])
    {
        const int j = t;              // 0..255
        float a[ROWS];
        #pragma unroll
        for (int r = 0; r < ROWS; r++) a[r] = 0.f;
        for (int k = 0; k < NBITS; k++) {
            float w = v_w1[(NBITS + k) * NHV + j];
            #pragma unroll
            for (int r = 0; r < ROWS; r++)
                a[r] = fmaf(sms[r][k], w, a[r]);
        }
        #pragma unroll
        for (int r = 0; r < ROWS; r++)
            g_vs[(b0 + r) * NHV + j] = a[r];
    }
}

// ---------------------------------------------------------------------------
// Kernel 2: per-batch fused chain. One block per b; 256 threads (16x16),
// each thread computes a 4x4 microtile. 183808 B dynamic smem, 1 CTA/SM.
// ---------------------------------------------------------------------------
__global__ __launch_bounds__(256, 1) void main_kernel(
    const float* __restrict__ a_bits,
    const float* __restrict__ ix_w1, const float* __restrict__ ix_b1,
    const float* __restrict__ ix_w2, const float* __restrict__ ix_b2,
    const float* __restrict__ ix_w3, const float* __restrict__ ix_b3,
    const float* __restrict__ v_w1,  const float* __restrict__ v_b1,
    const float* __restrict__ v_w2,  const float* __restrict__ v_b2,
    float* __restrict__ out)
{
    extern __shared__ float sm[];
    float* h1s  = sm;            // 64*516  = 33024
    float* w2s  = sm + 33024;    // 32*64   = 2048
    float* h2s  = sm + 35072;    // 64*68   = 4352
    float* w3s  = sm + 39424;    // 64*64   = 4096
    float* sp_s = sm + 43520;    // 512
    float* b1s  = sm + 44032;    // 512
    float* b2s  = sm + 44544;    // 512
    float* b3s  = sm + 45056;    // 64
    float* ab_s = sm + 45120;    // 64
    float* vs_s = sm + 45184;    // 256
    float* vb1s = sm + 45440;    // 256
    float* vw2s = sm + 45696;    // 256  -> total 45952 floats

    const int t  = threadIdx.x;
    const int b  = blockIdx.x;
    const int tx = t & 15;
    const int ty = t >> 4;
    const int ty4 = ty * 4;

    for (int i = t; i < NH; i += 256) {
        sp_s[i] = g_sp[b * NH + i];
        b1s[i]  = ix_b1[i];
        b2s[i]  = ix_b2[i];
    }
    for (int i = t; i < NHV; i += 256) {
        vs_s[i]  = g_vs[b * NHV + i];
        vb1s[i]  = v_b1[i];
        vw2s[i]  = v_w2[i];
    }
    if (t < NBITS) { b3s[t] = ix_b3[t]; ab_s[t] = a_bits[b * NBITS + t]; }
    __syncthreads();

    // build h1s[i][k] = relu(pos[i][k] + shift_part[k] + ix_b1[k])
    for (int f4 = t; f4 < NBITS * (NH / 4); f4 += 256) {
        int i  = f4 >> 7;           // / 128
        int kf = f4 & 127;
        float4 p  = ((const float4*)ix_w1)[i * (NH / 4) + kf];
        float4 s  = ((const float4*)sp_s)[kf];
        float4 bb = ((const float4*)b1s)[kf];
        float4 r;
        r.x = fmaxf(p.x + s.x + bb.x, 0.f);
        r.y = fmaxf(p.y + s.y + bb.y, 0.f);
        r.z = fmaxf(p.z + s.z + bb.z, 0.f);
        r.w = fmaxf(p.w + s.w + bb.w, 0.f);
        *(float4*)&h1s[i * STR + kf * 4] = r;
    }
    __syncthreads();

    float lg[4][4];
    #pragma unroll
    for (int r = 0; r < 4; r++)
        #pragma unroll
        for (int cc = 0; cc < 4; cc++) lg[r][cc] = 0.f;

    for (int nb = 0; nb < 8; nb++) {
        const int nbase = nb * 64;
        float c[4][4];
        #pragma unroll
        for (int r = 0; r < 4; r++)
            #pragma unroll
            for (int cc = 0; cc < 4; cc++) c[r][cc] = 0.f;

        // GEMM1: c[64,64] = h1s[64,512] @ W2[:, nbase:nbase+64]
        for (int kk = 0; kk < 16; kk++) {
            const int kb = kk * 32;
            #pragma unroll
            for (int p = 0; p < 2; p++) {
                int idx = t + p * 256;            // 0..511 float4
                int row = idx >> 4, c4 = idx & 15;
                ((float4*)w2s)[idx] =
                    ((const float4*)ix_w2)[((kb + row) * NH + nbase) / 4 + c4];
            }
            __syncthreads();
            // K in chunks of 4: float4 loads for both A rows and B columns.
            // 8 x LDS.128 per 64 FMA (was 20 LDS-issues per 64 FMA).
            #pragma unroll
            for (int k4 = 0; k4 < 8; k4++) {
                const int kq = k4 * 4;
                float4 bv0 = *(const float4*)&w2s[(kq + 0) * 64 + tx * 4];
                float4 bv1 = *(const float4*)&w2s[(kq + 1) * 64 + tx * 4];
                float4 bv2 = *(const float4*)&w2s[(kq + 2) * 64 + tx * 4];
                float4 bv3 = *(const float4*)&w2s[(kq + 3) * 64 + tx * 4];
                #pragma unroll
                for (int r = 0; r < 4; r++) {
                    float4 av = *(const float4*)&h1s[(ty4 + r) * STR + kb + kq];
                    c[r][0]=fmaf(av.x,bv0.x,c[r][0]); c[r][1]=fmaf(av.x,bv0.y,c[r][1]);
                    c[r][2]=fmaf(av.x,bv0.z,c[r][2]); c[r][3]=fmaf(av.x,bv0.w,c[r][3]);
                    c[r][0]=fmaf(av.y,bv1.x,c[r][0]); c[r][1]=fmaf(av.y,bv1.y,c[r][1]);
                    c[r][2]=fmaf(av.y,bv1.z,c[r][2]); c[r][3]=fmaf(av.y,bv1.w,c[r][3]);
                    c[r][0]=fmaf(av.z,bv2.x,c[r][0]); c[r][1]=fmaf(av.z,bv2.y,c[r][1]);
                    c[r][2]=fmaf(av.z,bv2.z,c[r][2]); c[r][3]=fmaf(av.z,bv2.w,c[r][3]);
                    c[r][0]=fmaf(av.w,bv3.x,c[r][0]); c[r][1]=fmaf(av.w,bv3.y,c[r][1]);
                    c[r][2]=fmaf(av.w,bv3.z,c[r][2]); c[r][3]=fmaf(av.w,bv3.w,c[r][3]);
                }
            }
            __syncthreads();
        }

        // h2 chunk = relu(c + b2), stage to smem; stage W3 rows for this chunk
        #pragma unroll
        for (int r = 0; r < 4; r++)
            #pragma unroll
            for (int cc = 0; cc < 4; cc++) {
                float v = fmaxf(c[r][cc] + b2s[nbase + tx * 4 + cc], 0.f);
                h2s[(ty4 + r) * 68 + tx * 4 + cc] = v;
            }
        #pragma unroll
        for (int p = 0; p < 4; p++) {
            int idx = t + p * 256;                // 0..1023 float4
            int row = idx >> 4, c4 = idx & 15;
            ((float4*)w3s)[idx] =
                ((const float4*)ix_w3)[((nbase + row) * NBITS) / 4 + c4];
        }
        __syncthreads();

        // GEMM2 accumulate: logits[64,64] += h2chunk[64,64] @ W3chunk[64,64]
        #pragma unroll
        for (int k4 = 0; k4 < 16; k4++) {
            const int kq = k4 * 4;
            float4 bv0 = *(const float4*)&w3s[(kq + 0) * 64 + tx * 4];
            float4 bv1 = *(const float4*)&w3s[(kq + 1) * 64 + tx * 4];
            float4 bv2 = *(const float4*)&w3s[(kq + 2) * 64 + tx * 4];
            float4 bv3 = *(const float4*)&w3s[(kq + 3) * 64 + tx * 4];
            #pragma unroll
            for (int r = 0; r < 4; r++) {
                float4 av = *(const float4*)&h2s[(ty4 + r) * 68 + kq];
                lg[r][0]=fmaf(av.x,bv0.x,lg[r][0]); lg[r][1]=fmaf(av.x,bv0.y,lg[r][1]);
                lg[r][2]=fmaf(av.x,bv0.z,lg[r][2]); lg[r][3]=fmaf(av.x,bv0.w,lg[r][3]);
                lg[r][0]=fmaf(av.y,bv1.x,lg[r][0]); lg[r][1]=fmaf(av.y,bv1.y,lg[r][1]);
                lg[r][2]=fmaf(av.y,bv1.z,lg[r][2]); lg[r][3]=fmaf(av.y,bv1.w,lg[r][3]);
                lg[r][0]=fmaf(av.z,bv2.x,lg[r][0]); lg[r][1]=fmaf(av.z,bv2.y,lg[r][1]);
                lg[r][2]=fmaf(av.z,bv2.z,lg[r][2]); lg[r][3]=fmaf(av.z,bv2.w,lg[r][3]);
                lg[r][0]=fmaf(av.w,bv3.x,lg[r][0]); lg[r][1]=fmaf(av.w,bv3.y,lg[r][1]);
                lg[r][2]=fmaf(av.w,bv3.z,lg[r][2]); lg[r][3]=fmaf(av.w,bv3.w,lg[r][3]);
            }
        }
        __syncthreads();
    }

    // epilogue: +b3, softmax over cols, pointed = soft @ a_bits, valid head, sigmoid
    const float vb2 = v_b2[0];
    #pragma unroll
    for (int r = 0; r < 4; r++) {
        const int R = ty4 + r;
        float l0 = lg[r][0] + b3s[tx * 4 + 0];
        float l1 = lg[r][1] + b3s[tx * 4 + 1];
        float l2 = lg[r][2] + b3s[tx * 4 + 2];
        float l3 = lg[r][3] + b3s[tx * 4 + 3];

        float m = fmaxf(fmaxf(l0, l1), fmaxf(l2, l3));
        #pragma unroll
        for (int o = 8; o > 0; o >>= 1) m = fmaxf(m, __shfl_xor_sync(0xffffffffu, m, o));

        float e0 = expf(l0 - m), e1 = expf(l1 - m), e2 = expf(l2 - m), e3 = expf(l3 - m);
        float den = e0 + e1 + e2 + e3;
        float num = e0 * ab_s[tx * 4 + 0] + e1 * ab_s[tx * 4 + 1]
                  + e2 * ab_s[tx * 4 + 2] + e3 * ab_s[tx * 4 + 3];
        #pragma unroll
        for (int o = 8; o > 0; o >>= 1) {
            den += __shfl_xor_sync(0xffffffffu, den, o);
            num += __shfl_xor_sync(0xffffffffu, num, o);
        }
        float pointed = num / den;

        // valid head: 16 j's per lane
        float acc = 0.f;
        #pragma unroll 4
        for (int jj = 0; jj < 16; jj++) {
            int j = tx * 16 + jj;
            float vh = fmaxf(v_w1[R * NHV + j] + vs_s[j] + vb1s[j], 0.f);
            acc = fmaf(vh, vw2s[j], acc);
        }
        #pragma unroll
        for (int o = 8; o > 0; o >>= 1) acc += __shfl_xor_sync(0xffffffffu, acc, o);

        if (tx == 0) {
            float vlog = acc + vb2;
            out[b * NBITS + R] = pointed * (1.f / (1.f + expf(-vlog)));
        }
    }
}

// ---------------------------------------------------------------------------
extern "C" void kernel_launch(void* const* d_in, const int* in_sizes, int n_in,
                              void* d_out, int out_size)
{
    const float* a_bits     = (const float*)d_in[0];
    const float* shift_bits = (const float*)d_in[1];
    const float* sd_w1 = (const float*)d_in[2];
    const float* sd_b1 = (const float*)d_in[3];
    const float* sd_w2 = (const float*)d_in[4];
    const float* sd_b2 = (const float*)d_in[5];
    const float* sd_w3 = (const float*)d_in[6];
    const float* sd_b3 = (const float*)d_in[7];
    const float* ix_w1 = (const float*)d_in[8];
    const float* ix_b1 = (const float*)d_in[9];
    const float* ix_w2 = (const float*)d_in[10];
    const float* ix_b2 = (const float*)d_in[11];
    const float* ix_w3 = (const float*)d_in[12];
    const float* ix_b3 = (const float*)d_in[13];
    const float* v_w1  = (const float*)d_in[14];
    const float* v_b1  = (const float*)d_in[15];
    const float* v_w2  = (const float*)d_in[16];
    const float* v_b2  = (const float*)d_in[17];
    float* out = (float*)d_out;

    const int dyn_smem = 45952 * (int)sizeof(float);   // 183808 B
    cudaFuncSetAttribute(main_kernel,
                         cudaFuncAttributeMaxDynamicSharedMemorySize, dyn_smem);

    shift_net_kernel<<<NB / 8, 256>>>(shift_bits, sd_w1, sd_b1, sd_w2, sd_b2,
                                      sd_w3, sd_b3, ix_w1, v_w1);
    main_kernel<<<NB, 256, dyn_smem>>>(a_bits, ix_w1, ix_b1, ix_w2, ix_b2,
                                       ix_w3, ix_b3, v_w1, v_b1, v_w2, v_b2, out);
}

// round 4
// speedup vs baseline: 1.1417x; 1.1417x over previous
#include <cuda_runtime.h>
#include <math.h>

#define NB    2048
#define NBITS 64
#define NH    512
#define NHV   256
#define STR   516   // padded row stride for h1s (floats, even, 16B-aligned rows)

typedef unsigned long long ull;

// Scratch (device globals: no allocation allowed in kernel_launch)
__device__ float g_sp[NB * NH];    // shift_part = shift_soft @ ix_w1[64:]
__device__ float g_vs[NB * NHV];   // v_shift    = shift_soft @ v_w1[64:]

// packed f32x2 fma: c.{lo,hi} += a.{lo,hi} * b.{lo,hi}   (Blackwell FFMA2)
__device__ __forceinline__ void ffma2(ull& c, ull a, ull b) {
    asm("fma.rn.f32x2 %0, %1, %2, %0;" : "+l"(c) : "l"(a), "l"(b));
}
__device__ __forceinline__ float2 f2unpack(ull v) {
    float2 r; asm("mov.b64 {%0,%1}, %2;" : "=f"(r.x), "=f"(r.y) : "l"(v)); return r;
}

// ---------------------------------------------------------------------------
// Kernel 1: shift MLP + softmax + shift_part/v_shift projections.
// One block handles 8 batch rows; 256 threads. (small: ~2% of runtime)
// ---------------------------------------------------------------------------
__global__ __launch_bounds__(256) void shift_net_kernel(
    const float* __restrict__ shift_bits,
    const float* __restrict__ sd_w1, const float* __restrict__ sd_b1,
    const float* __restrict__ sd_w2, const float* __restrict__ sd_b2,
    const float* __restrict__ sd_w3, const float* __restrict__ sd_b3,
    const float* __restrict__ ix_w1, const float* __restrict__ v_w1)
{
    const int ROWS = 8;
    __shared__ float xs[ROWS][NBITS];
    __shared__ float hs[ROWS][NH];
    __shared__ float gs[ROWS][NH];
    __shared__ float lgs[ROWS][NBITS];
    __shared__ float sms[ROWS][NBITS];

    const int t  = threadIdx.x;
    const int b0 = blockIdx.x * ROWS;

    for (int idx = t; idx < ROWS * NBITS; idx += 256) {
        int r = idx >> 6, k = idx & 63;
        xs[r][k] = shift_bits[(b0 + r) * NBITS + k];
    }
    __syncthreads();

    {   // layer 1
        const int j0 = t, j1 = t + 256;
        float a0[ROWS], a1[ROWS];
        #pragma unroll
        for (int r = 0; r < ROWS; r++) { a0[r] = 0.f; a1[r] = 0.f; }
        for (int k = 0; k < NBITS; k++) {
            float w0 = sd_w1[k * NH + j0];
            float w1 = sd_w1[k * NH + j1];
            #pragma unroll
            for (int r = 0; r < ROWS; r++) {
                a0[r] = fmaf(xs[r][k], w0, a0[r]);
                a1[r] = fmaf(xs[r][k], w1, a1[r]);
            }
        }
        float bb0 = sd_b1[j0], bb1 = sd_b1[j1];
        #pragma unroll
        for (int r = 0; r < ROWS; r++) {
            hs[r][j0] = fmaxf(a0[r] + bb0, 0.f);
            hs[r][j1] = fmaxf(a1[r] + bb1, 0.f);
        }
    }
    __syncthreads();

    {   // layer 2
        const int j0 = t, j1 = t + 256;
        float a0[ROWS], a1[ROWS];
        #pragma unroll
        for (int r = 0; r < ROWS; r++) { a0[r] = 0.f; a1[r] = 0.f; }
        for (int k = 0; k < NH; k++) {
            float w0 = sd_w2[k * NH + j0];
            float w1 = sd_w2[k * NH + j1];
            #pragma unroll
            for (int r = 0; r < ROWS; r++) {
                a0[r] = fmaf(hs[r][k], w0, a0[r]);
                a1[r] = fmaf(hs[r][k], w1, a1[r]);
            }
        }
        float bb0 = sd_b2[j0], bb1 = sd_b2[j1];
        #pragma unroll
        for (int r = 0; r < ROWS; r++) {
            gs[r][j0] = fmaxf(a0[r] + bb0, 0.f);
            gs[r][j1] = fmaxf(a1[r] + bb1, 0.f);
        }
    }
    __syncthreads();

    // layer 3
    #pragma unroll
    for (int p = 0; p < 2; p++) {
        int idx = t + p * 256;
        int r = idx >> 6, j = idx & 63;
        float acc = 0.f;
        for (int k = 0; k < NH; k++)
            acc = fmaf(gs[r][k], sd_w3[k * NBITS + j], acc);
        lgs[r][j] = acc + sd_b3[j];
    }
    __syncthreads();

    {   // softmax over 64, warp w -> row w
        int w = t >> 5, l = t & 31;
        float v0 = lgs[w][l], v1 = lgs[w][l + 32];
        float m = fmaxf(v0, v1);
        #pragma unroll
        for (int o = 16; o > 0; o >>= 1) m = fmaxf(m, __shfl_xor_sync(0xffffffffu, m, o));
        float e0 = expf(v0 - m), e1 = expf(v1 - m);
        float s = e0 + e1;
        #pragma unroll
        for (int o = 16; o > 0; o >>= 1) s += __shfl_xor_sync(0xffffffffu, s, o);
        float inv = 1.f / s;
        sms[w][l] = e0 * inv;
        sms[w][l + 32] = e1 * inv;
    }
    __syncthreads();

    {   // shift_part = soft @ ix_w1[64:128]
        const int j0 = t, j1 = t + 256;
        float a0[ROWS], a1[ROWS];
        #pragma unroll
        for (int r = 0; r < ROWS; r++) { a0[r] = 0.f; a1[r] = 0.f; }
        for (int k = 0; k < NBITS; k++) {
            float w0 = ix_w1[(NBITS + k) * NH + j0];
            float w1 = ix_w1[(NBITS + k) * NH + j1];
            #pragma unroll
            for (int r = 0; r < ROWS; r++) {
                a0[r] = fmaf(sms[r][k], w0, a0[r]);
                a1[r] = fmaf(sms[r][k], w1, a1[r]);
            }
        }
        #pragma unroll
        for (int r = 0; r < ROWS; r++) {
            g_sp[(b0 + r) * NH + j0] = a0[r];
            g_sp[(b0 + r) * NH + j1] = a1[r];
        }
    }

    {   // v_shift = soft @ v_w1[64:128]
        const int j = t;
        float a[ROWS];
        #pragma unroll
        for (int r = 0; r < ROWS; r++) a[r] = 0.f;
        for (int k = 0; k < NBITS; k++) {
            float w = v_w1[(NBITS + k) * NHV + j];
            #pragma unroll
            for (int r = 0; r < ROWS; r++)
                a[r] = fmaf(sms[r][k], w, a[r]);
        }
        #pragma unroll
        for (int r = 0; r < ROWS; r++)
            g_vs[(b0 + r) * NHV + j] = a[r];
    }
}

// ---------------------------------------------------------------------------
// Kernel 2: per-batch fused chain with packed f32x2 FMA (FFMA2).
// 256 threads (16x16). Microtile 4 rows x 8 cols; f32x2 lanes = (even k, odd k).
// W2/W3 staged k-pair-interleaved so B loads are natural LDS.64.
// ---------------------------------------------------------------------------
__global__ __launch_bounds__(256, 1) void main_kernel(
    const float* __restrict__ a_bits,
    const float* __restrict__ ix_w1, const float* __restrict__ ix_b1,
    const float* __restrict__ ix_w2, const float* __restrict__ ix_b2,
    const float* __restrict__ ix_w3, const float* __restrict__ ix_b3,
    const float* __restrict__ v_w1,  const float* __restrict__ v_b1,
    const float* __restrict__ v_w2,  const float* __restrict__ v_b2,
    float* __restrict__ out)
{
    extern __shared__ float sm[];
    float* h1s  = sm;            // 64*516            = 33024
    float* w2p  = sm + 33024;    // 16 kpair * 256    =  4096  (k-interleaved W2 tile)
    float* h2s  = sm + 37120;    // 64*132            =  8448
    float* w3p  = sm + 45568;    // 64 kpair * 128    =  8192  (k-interleaved W3 chunk)
    float* sp_s = sm + 53760;    // 512  (shift_part + ix_b1 folded)
    float* b2s  = sm + 54272;    // 512
    float* b3s  = sm + 54784;    // 64
    float* ab_s = sm + 54848;    // 64
    float* vs_s = sm + 54912;    // 256
    float* vb1s = sm + 55168;    // 256
    float* vw2s = sm + 55424;    // 256   -> total 55680 floats = 222720 B

    const int t  = threadIdx.x;
    const int b  = blockIdx.x;
    const int tx = t & 15;        // col group: cols tx + 16*m
    const int ty = t >> 4;        // row group: rows ty*4 .. +3
    const int row0 = ty * 4;

    for (int i = t; i < NH; i += 256) {
        sp_s[i] = g_sp[b * NH + i] + ix_b1[i];   // fold bias
        b2s[i]  = ix_b2[i];
    }
    for (int i = t; i < NHV; i += 256) {
        vs_s[i]  = g_vs[b * NHV + i];
        vb1s[i]  = v_b1[i];
        vw2s[i]  = v_w2[i];
    }
    if (t < NBITS) { b3s[t] = ix_b3[t]; ab_s[t] = a_bits[b * NBITS + t]; }
    __syncthreads();

    // build h1s[i][k] = relu(pos[i][k] + sp_s[k])   (row-major, stride STR)
    for (int f4 = t; f4 < NBITS * (NH / 4); f4 += 256) {
        int i  = f4 >> 7;
        int kf = f4 & 127;
        float4 p = ((const float4*)ix_w1)[i * (NH / 4) + kf];
        float4 s = ((const float4*)sp_s)[kf];
        float4 r;
        r.x = fmaxf(p.x + s.x, 0.f);
        r.y = fmaxf(p.y + s.y, 0.f);
        r.z = fmaxf(p.z + s.z, 0.f);
        r.w = fmaxf(p.w + s.w, 0.f);
        *(float4*)&h1s[i * STR + kf * 4] = r;
    }
    // (covered by syncs inside the tile loop before first compute)

    const ull* h1p = (const ull*)h1s;   // h1s in k-pairs: row stride STR/2 = 258
    const ull* w2q = (const ull*)w2p;   // [kpair][col] : row stride 128
    const ull* h2q = (const ull*)h2s;   // row stride 66
    const ull* w3q = (const ull*)w3p;   // [kpair][col] : row stride 64

    // prefetch registers for W2 tile staging (tile tt = nb*16 + kk)
    const int u0 = t, u1 = t + 256;
    const int kpa = u0 >> 5, cqa = u0 & 31;   // unit A: (kpair, col-quad)
    const int kpb = u1 >> 5, cqb = u1 & 31;   // unit B
    float4 plo0, phi0, plo1, phi1;
    {
        // tile 0: nbase=0, kb=0
        plo0 = *(const float4*)&ix_w2[(2 * kpa    ) * NH + cqa * 4];
        phi0 = *(const float4*)&ix_w2[(2 * kpa + 1) * NH + cqa * 4];
        plo1 = *(const float4*)&ix_w2[(2 * kpb    ) * NH + cqb * 4];
        phi1 = *(const float4*)&ix_w2[(2 * kpb + 1) * NH + cqb * 4];
    }

    ull lg2[4][4];   // logits accumulators (f32x2 = even/odd-k partial sums)
    #pragma unroll
    for (int r = 0; r < 4; r++)
        #pragma unroll
        for (int m = 0; m < 4; m++) lg2[r][m] = 0ull;

    for (int nb = 0; nb < 4; nb++) {
        const int nbase = nb * 128;

        ull c2[4][8];
        #pragma unroll
        for (int r = 0; r < 4; r++)
            #pragma unroll
            for (int m = 0; m < 8; m++) c2[r][m] = 0ull;

        for (int kk = 0; kk < 16; kk++) {
            __syncthreads();   // previous tile fully consumed
            // stage w2p (k-pair interleaved) from prefetch regs
            {
                int w = kpa * 256 + cqa * 8;
                *(float4*)&w2p[w]     = make_float4(plo0.x, phi0.x, plo0.y, phi0.y);
                *(float4*)&w2p[w + 4] = make_float4(plo0.z, phi0.z, plo0.w, phi0.w);
                w = kpb * 256 + cqb * 8;
                *(float4*)&w2p[w]     = make_float4(plo1.x, phi1.x, plo1.y, phi1.y);
                *(float4*)&w2p[w + 4] = make_float4(plo1.z, phi1.z, plo1.w, phi1.w);
            }
            __syncthreads();
            // prefetch next tile (hidden under compute below)
            {
                int tt = nb * 16 + kk + 1;
                if (tt < 64) {
                    int nbn = (tt >> 4) * 128;
                    int kbn = (tt & 15) * 32;
                    plo0 = *(const float4*)&ix_w2[(kbn + 2 * kpa    ) * NH + nbn + cqa * 4];
                    phi0 = *(const float4*)&ix_w2[(kbn + 2 * kpa + 1) * NH + nbn + cqa * 4];
                    plo1 = *(const float4*)&ix_w2[(kbn + 2 * kpb    ) * NH + nbn + cqb * 4];
                    phi1 = *(const float4*)&ix_w2[(kbn + 2 * kpb + 1) * NH + nbn + cqb * 4];
                }
            }
            // compute: 16 k-pairs against this tile
            const int kbp = kk * 16;   // k-pair base within h1 row (in ull units)
            #pragma unroll 4
            for (int kp2 = 0; kp2 < 8; kp2++) {
                ull b0[8], b1[8];
                #pragma unroll
                for (int m = 0; m < 8; m++) {
                    b0[m] = w2q[(2 * kp2    ) * 128 + tx + 16 * m];
                    b1[m] = w2q[(2 * kp2 + 1) * 128 + tx + 16 * m];
                }
                #pragma unroll
                for (int r = 0; r < 4; r++) {
                    ull a0 = h1p[(row0 + r) * 258 + kbp + kp2 * 2];
                    ull a1 = h1p[(row0 + r) * 258 + kbp + kp2 * 2 + 1];
                    #pragma unroll
                    for (int m = 0; m < 8; m++) {
                        ffma2(c2[r][m], a0, b0[m]);
                        ffma2(c2[r][m], a1, b1[m]);
                    }
                }
            }
        }

        // h2 chunk = relu(hadd(c2) + b2) -> h2s (row-major, stride 132)
        #pragma unroll
        for (int r = 0; r < 4; r++)
            #pragma unroll
            for (int m = 0; m < 8; m++) {
                float2 v = f2unpack(c2[r][m]);
                int c = tx + 16 * m;
                float h = fmaxf(v.x + v.y + b2s[nbase + c], 0.f);
                h2s[(row0 + r) * 132 + c] = h;
            }
        // stage w3p (k-pair interleaved) for rows nbase..nbase+127
        #pragma unroll
        for (int p = 0; p < 4; p++) {
            int u  = t + p * 256;
            int kp = u >> 4, cq = u & 15;
            float4 lo = *(const float4*)&ix_w3[(nbase + 2 * kp    ) * NBITS + cq * 4];
            float4 hi = *(const float4*)&ix_w3[(nbase + 2 * kp + 1) * NBITS + cq * 4];
            *(float4*)&w3p[kp * 128 + cq * 8]     = make_float4(lo.x, hi.x, lo.y, hi.y);
            *(float4*)&w3p[kp * 128 + cq * 8 + 4] = make_float4(lo.z, hi.z, lo.w, hi.w);
        }
        __syncthreads();

        // GEMM2 partial: logits += h2chunk[64,128] @ W3[nbase:+128, 64]
        #pragma unroll 4
        for (int kp = 0; kp < 64; kp++) {
            ull bb[4];
            #pragma unroll
            for (int m = 0; m < 4; m++) bb[m] = w3q[kp * 64 + tx + 16 * m];
            #pragma unroll
            for (int r = 0; r < 4; r++) {
                ull aa = h2q[(row0 + r) * 66 + kp];
                #pragma unroll
                for (int m = 0; m < 4; m++) ffma2(lg2[r][m], aa, bb[m]);
            }
        }
        // next nb's tile-loop syncs protect h2s/w3p reuse
    }

    // epilogue: +b3, softmax over 64 cols, pointed, valid head, sigmoid
    const float vb2 = v_b2[0];
    #pragma unroll
    for (int r = 0; r < 4; r++) {
        const int R = row0 + r;
        float l[4], ab[4];
        #pragma unroll
        for (int m = 0; m < 4; m++) {
            float2 v = f2unpack(lg2[r][m]);
            int c = tx + 16 * m;
            l[m]  = v.x + v.y + b3s[c];
            ab[m] = ab_s[c];
        }
        float mx = fmaxf(fmaxf(l[0], l[1]), fmaxf(l[2], l[3]));
        #pragma unroll
        for (int o = 8; o > 0; o >>= 1) mx = fmaxf(mx, __shfl_xor_sync(0xffffffffu, mx, o));

        float e0 = expf(l[0] - mx), e1 = expf(l[1] - mx),
              e2 = expf(l[2] - mx), e3 = expf(l[3] - mx);
        float den = e0 + e1 + e2 + e3;
        float num = e0 * ab[0] + e1 * ab[1] + e2 * ab[2] + e3 * ab[3];
        #pragma unroll
        for (int o = 8; o > 0; o >>= 1) {
            den += __shfl_xor_sync(0xffffffffu, den, o);
            num += __shfl_xor_sync(0xffffffffu, num, o);
        }
        float pointed = num / den;

        float acc = 0.f;
        #pragma unroll 4
        for (int jj = 0; jj < 16; jj++) {
            int j = tx * 16 + jj;
            float vh = fmaxf(v_w1[R * NHV + j] + vs_s[j] + vb1s[j], 0.f);
            acc = fmaf(vh, vw2s[j], acc);
        }
        #pragma unroll
        for (int o = 8; o > 0; o >>= 1) acc += __shfl_xor_sync(0xffffffffu, acc, o);

        if (tx == 0) {
            float vlog = acc + vb2;
            out[b * NBITS + R] = pointed * (1.f / (1.f + expf(-vlog)));
        }
    }
}

// ---------------------------------------------------------------------------
extern "C" void kernel_launch(void* const* d_in, const int* in_sizes, int n_in,
                              void* d_out, int out_size)
{
    const float* a_bits     = (const float*)d_in[0];
    const float* shift_bits = (const float*)d_in[1];
    const float* sd_w1 = (const float*)d_in[2];
    const float* sd_b1 = (const float*)d_in[3];
    const float* sd_w2 = (const float*)d_in[4];
    const float* sd_b2 = (const float*)d_in[5];
    const float* sd_w3 = (const float*)d_in[6];
    const float* sd_b3 = (const float*)d_in[7];
    const float* ix_w1 = (const float*)d_in[8];
    const float* ix_b1 = (const float*)d_in[9];
    const float* ix_w2 = (const float*)d_in[10];
    const float* ix_b2 = (const float*)d_in[11];
    const float* ix_w3 = (const float*)d_in[12];
    const float* ix_b3 = (const float*)d_in[13];
    const float* v_w1  = (const float*)d_in[14];
    const float* v_b1  = (const float*)d_in[15];
    const float* v_w2  = (const float*)d_in[16];
    const float* v_b2  = (const float*)d_in[17];
    float* out = (float*)d_out;

    const int dyn_smem = 55680 * (int)sizeof(float);   // 222720 B
    cudaFuncSetAttribute(main_kernel,
                         cudaFuncAttributeMaxDynamicSharedMemorySize, dyn_smem);

    shift_net_kernel<<<NB / 8, 256>>>(shift_bits, sd_w1, sd_b1, sd_w2, sd_b2,
                                      sd_w3, sd_b3, ix_w1, v_w1);
    main_kernel<<<NB, 256, dyn_smem>>>(a_bits, ix_w1, ix_b1, ix_w2, ix_b2,
                                       ix_w3, ix_b3, v_w1, v_b1, v_w2, v_b2, out);
}

// round 6
// speedup vs baseline: 6.1411x; 5.3792x over previous
#include <cuda_runtime.h>
#include <cuda_bf16.h>
#include <math.h>
#include <stdint.h>

#define NB    2048
#define NBITS 64
#define NH    512
#define NHV   256

// ---------------------------------------------------------------------------
// Device scratch (no allocation allowed anywhere)
// ---------------------------------------------------------------------------
__device__ float g_sp[NB * NH];               // shift_part (per batch)
__device__ float g_vs[NB * NHV];              // v_shift (per batch)
__device__ __nv_bfloat16 g_w2bf[NH * NH];     // W2^T bf16  [n][k]
__device__ __nv_bfloat16 g_w3bf[NBITS * NH];  // W3^T bf16  [n3][k]

// ---------------------------------------------------------------------------
// Helpers
// ---------------------------------------------------------------------------
__device__ __forceinline__ uint32_t smem_u32(const void* p) {
    uint32_t a;
    asm("{ .reg .u64 t; cvta.to.shared.u64 t, %1; cvt.u32.u64 %0, t; }"
        : "=r"(a) : "l"(p));
    return a;
}
__device__ __forceinline__ uint32_t pack_bf16x2(float lo, float hi) {
    uint32_t r;
    asm("cvt.rn.bf16x2.f32 %0, %1, %2;" : "=r"(r) : "f"(hi), "f"(lo));
    return r;
}
__device__ __forceinline__ void cp16(uint32_t dst, const void* src) {
    asm volatile("cp.async.cg.shared.global [%0], [%1], 16;"
                 :: "r"(dst), "l"(src) : "memory");
}
__device__ __forceinline__ void mma_bf16(float* c, const uint32_t* a,
                                         uint32_t b0, uint32_t b1) {
    asm volatile("mma.sync.aligned.m16n8k16.row.col.f32.bf16.bf16.f32 "
                 "{%0,%1,%2,%3}, {%4,%5,%6,%7}, {%8,%9}, {%0,%1,%2,%3};"
                 : "+f"(c[0]), "+f"(c[1]), "+f"(c[2]), "+f"(c[3])
                 : "r"(a[0]), "r"(a[1]), "r"(a[2]), "r"(a[3]),
                   "r"(b0), "r"(b1));
}

// SMEM byte offsets (dynamic smem base)
#define H1_OFF   0         // 128 rows x (520 bf16 = 1040 B) = 133120
#define W2_OFF   133120    // 2 bufs x 128 rows x (136 bf16 = 272 B) = 69632
#define W2_TILE  34816
#define W3_OFF   202752    // 64 rows x 272 B = 17408
#define B2_OFF   220160    // 512 f32
#define B3_OFF   222208    // 64 f32
#define AB_OFF   222464    // 128 f32
#define VS_OFF   222976    // 512 f32
#define VW2_OFF  225024    // 256 f32
#define SM_TOTAL 226048

// ---------------------------------------------------------------------------
// Prep kernels: transpose + bf16 convert (plain [n][k] layouts).
// ---------------------------------------------------------------------------
__global__ void prep_w2_kernel(const float* __restrict__ ix_w2) {
    int idx = blockIdx.x * 256 + threadIdx.x;          // 0..262143
    int n = idx >> 9, k = idx & 511;
    g_w2bf[n * NH + k] = __float2bfloat16(ix_w2[k * NH + n]);
}
__global__ void prep_w3_kernel(const float* __restrict__ ix_w3) {
    int idx = blockIdx.x * 256 + threadIdx.x;          // 0..32767
    int n3 = idx >> 9, k = idx & 511;
    g_w3bf[n3 * NH + k] = __float2bfloat16(ix_w3[k * NBITS + n3]);
}

// ---------------------------------------------------------------------------
// Kernel 1: shift MLP + softmax + shift_part/v_shift projections (unchanged).
// ---------------------------------------------------------------------------
__global__ __launch_bounds__(256) void shift_net_kernel(
    const float* __restrict__ shift_bits,
    const float* __restrict__ sd_w1, const float* __restrict__ sd_b1,
    const float* __restrict__ sd_w2, const float* __restrict__ sd_b2,
    const float* __restrict__ sd_w3, const float* __restrict__ sd_b3,
    const float* __restrict__ ix_w1, const float* __restrict__ v_w1)
{
    const int ROWS = 8;
    __shared__ float xs[ROWS][NBITS];
    __shared__ float hs[ROWS][NH];
    __shared__ float gs[ROWS][NH];
    __shared__ float lgs[ROWS][NBITS];
    __shared__ float sms[ROWS][NBITS];

    const int t  = threadIdx.x;
    const int b0 = blockIdx.x * ROWS;

    for (int idx = t; idx < ROWS * NBITS; idx += 256) {
        int r = idx >> 6, k = idx & 63;
        xs[r][k] = shift_bits[(b0 + r) * NBITS + k];
    }
    __syncthreads();

    {   // layer 1
        const int j0 = t, j1 = t + 256;
        float a0[ROWS], a1[ROWS];
        #pragma unroll
        for (int r = 0; r < ROWS; r++) { a0[r] = 0.f; a1[r] = 0.f; }
        for (int k = 0; k < NBITS; k++) {
            float w0 = sd_w1[k * NH + j0];
            float w1 = sd_w1[k * NH + j1];
            #pragma unroll
            for (int r = 0; r < ROWS; r++) {
                a0[r] = fmaf(xs[r][k], w0, a0[r]);
                a1[r] = fmaf(xs[r][k], w1, a1[r]);
            }
        }
        float bb0 = sd_b1[j0], bb1 = sd_b1[j1];
        #pragma unroll
        for (int r = 0; r < ROWS; r++) {
            hs[r][j0] = fmaxf(a0[r] + bb0, 0.f);
            hs[r][j1] = fmaxf(a1[r] + bb1, 0.f);
        }
    }
    __syncthreads();

    {   // layer 2
        const int j0 = t, j1 = t + 256;
        float a0[ROWS], a1[ROWS];
        #pragma unroll
        for (int r = 0; r < ROWS; r++) { a0[r] = 0.f; a1[r] = 0.f; }
        for (int k = 0; k < NH; k++) {
            float w0 = sd_w2[k * NH + j0];
            float w1 = sd_w2[k * NH + j1];
            #pragma unroll
            for (int r = 0; r < ROWS; r++) {
                a0[r] = fmaf(hs[r][k], w0, a0[r]);
                a1[r] = fmaf(hs[r][k], w1, a1[r]);
            }
        }
        float bb0 = sd_b2[j0], bb1 = sd_b2[j1];
        #pragma unroll
        for (int r = 0; r < ROWS; r++) {
            gs[r][j0] = fmaxf(a0[r] + bb0, 0.f);
            gs[r][j1] = fmaxf(a1[r] + bb1, 0.f);
        }
    }
    __syncthreads();

    #pragma unroll
    for (int p = 0; p < 2; p++) {   // layer 3
        int idx = t + p * 256;
        int r = idx >> 6, j = idx & 63;
        float acc = 0.f;
        for (int k = 0; k < NH; k++)
            acc = fmaf(gs[r][k], sd_w3[k * NBITS + j], acc);
        lgs[r][j] = acc + sd_b3[j];
    }
    __syncthreads();

    {   // softmax over 64
        int w = t >> 5, l = t & 31;
        float v0 = lgs[w][l], v1 = lgs[w][l + 32];
        float m = fmaxf(v0, v1);
        #pragma unroll
        for (int o = 16; o > 0; o >>= 1) m = fmaxf(m, __shfl_xor_sync(0xffffffffu, m, o));
        float e0 = expf(v0 - m), e1 = expf(v1 - m);
        float s = e0 + e1;
        #pragma unroll
        for (int o = 16; o > 0; o >>= 1) s += __shfl_xor_sync(0xffffffffu, s, o);
        float inv = 1.f / s;
        sms[w][l] = e0 * inv;
        sms[w][l + 32] = e1 * inv;
    }
    __syncthreads();

    {   // shift_part
        const int j0 = t, j1 = t + 256;
        float a0[ROWS], a1[ROWS];
        #pragma unroll
        for (int r = 0; r < ROWS; r++) { a0[r] = 0.f; a1[r] = 0.f; }
        for (int k = 0; k < NBITS; k++) {
            float w0 = ix_w1[(NBITS + k) * NH + j0];
            float w1 = ix_w1[(NBITS + k) * NH + j1];
            #pragma unroll
            for (int r = 0; r < ROWS; r++) {
                a0[r] = fmaf(sms[r][k], w0, a0[r]);
                a1[r] = fmaf(sms[r][k], w1, a1[r]);
            }
        }
        #pragma unroll
        for (int r = 0; r < ROWS; r++) {
            g_sp[(b0 + r) * NH + j0] = a0[r];
            g_sp[(b0 + r) * NH + j1] = a1[r];
        }
    }

    {   // v_shift
        const int j = t;
        float a[ROWS];
        #pragma unroll
        for (int r = 0; r < ROWS; r++) a[r] = 0.f;
        for (int k = 0; k < NBITS; k++) {
            float w = v_w1[(NBITS + k) * NHV + j];
            #pragma unroll
            for (int r = 0; r < ROWS; r++)
                a[r] = fmaf(sms[r][k], w, a[r]);
        }
        #pragma unroll
        for (int r = 0; r < ROWS; r++)
            g_vs[(b0 + r) * NHV + j] = a[r];
    }
}

// ---------------------------------------------------------------------------
// Kernel 2: mma.sync bf16 main chain. One CTA = 2 batches (M=128), 256 thr.
// ---------------------------------------------------------------------------
__global__ __launch_bounds__(256, 1) void main_mma_kernel(
    const float* __restrict__ a_bits,
    const float* __restrict__ ix_w1, const float* __restrict__ ix_b1,
    const float* __restrict__ ix_b2, const float* __restrict__ ix_b3,
    const float* __restrict__ v_w1,  const float* __restrict__ v_b1,
    const float* __restrict__ v_w2,  const float* __restrict__ v_b2,
    float* __restrict__ out)
{
    extern __shared__ char bp[];
    float* b2s  = (float*)(bp + B2_OFF);
    float* b3s  = (float*)(bp + B3_OFF);
    float* ab_s = (float*)(bp + AB_OFF);
    float* vs_s = (float*)(bp + VS_OFF);
    float* vw2s = (float*)(bp + VW2_OFF);

    const int t    = threadIdx.x;
    const int lane = t & 31, w = t >> 5;
    const int g = lane >> 2, tg = lane & 3;
    const int pair = blockIdx.x;
    const int m0 = w * 16;

    // ---- prologue: issue W2 chunk 0 (nb=0, kb=0) via cp.async ----
    {
        const __nv_bfloat16* src = g_w2bf;
        #pragma unroll
        for (int i = 0; i < 8; i++) {
            int idx = t + i * 256;
            int row = idx >> 4, c16 = idx & 15;
            cp16(smem_u32(bp + W2_OFF + row * 272 + c16 * 16),
                 src + row * NH + c16 * 8);
        }
        asm volatile("cp.async.commit_group;" ::: "memory");
    }

    // ---- misc staging ----
    for (int i = t; i < NH; i += 256) {
        b2s[i]  = ix_b2[i];
        vs_s[i] = g_vs[(2 * pair + (i >> 8)) * NHV + (i & 255)] + v_b1[i & 255];
    }
    vw2s[t] = v_w2[t];
    if (t < NBITS) b3s[t] = ix_b3[t];
    if (t < 128)   ab_s[t] = a_bits[(2 * pair + (t >> 6)) * NBITS + (t & 63)];

    // ---- h1 build: bf16 [128 rows][512 k], row stride 520 bf16 ----
    #pragma unroll 4
    for (int i = 0; i < 64; i++) {
        int idx = t + i * 256;           // 0..16383
        int m = idx >> 7, q = idx & 127;
        int k = q * 4;
        float4 p  = *(const float4*)(ix_w1 + (m & 63) * NH + k);
        float4 s  = *(const float4*)(g_sp + (2 * pair + (m >> 6)) * NH + k);
        float4 bb = *(const float4*)(ix_b1 + k);
        uint32_t lo = pack_bf16x2(fmaxf(p.x + s.x + bb.x, 0.f),
                                  fmaxf(p.y + s.y + bb.y, 0.f));
        uint32_t hi = pack_bf16x2(fmaxf(p.z + s.z + bb.z, 0.f),
                                  fmaxf(p.w + s.w + bb.w, 0.f));
        *(uint2*)(bp + H1_OFF + m * 1040 + k * 2) = make_uint2(lo, hi);
    }

    float lg[8][4];
    #pragma unroll
    for (int i = 0; i < 8; i++)
        #pragma unroll
        for (int j2 = 0; j2 < 4; j2++) lg[i][j2] = 0.f;

    float acc[16][4];

    const char* h1r0 = bp + H1_OFF + (m0 + g) * 1040;
    const char* h1r1 = h1r0 + 8 * 1040;

    for (int c = 0; c < 16; c++) {
        const int nb = c >> 2, kb = c & 3;
        const int next = c + 1;
        if (next < 16) {
            int nnb = next >> 2, nkb = next & 3;
            const __nv_bfloat16* src = g_w2bf + (nnb * 128) * NH + nkb * 128;
            char* dstb = bp + W2_OFF + (next & 1) * W2_TILE;
            #pragma unroll
            for (int i = 0; i < 8; i++) {
                int idx = t + i * 256;
                int row = idx >> 4, c16 = idx & 15;
                cp16(smem_u32(dstb + row * 272 + c16 * 16),
                     src + row * NH + c16 * 8);
            }
            if (nkb == 1) {   // stage W3 k-slice for nb=nnb (safe: after GEMM2(nnb-1))
                const __nv_bfloat16* s3 = g_w3bf + nnb * 128;
                #pragma unroll
                for (int i = 0; i < 4; i++) {
                    int idx = t + i * 256;
                    int row = idx >> 4, c16 = idx & 15;
                    cp16(smem_u32(bp + W3_OFF + row * 272 + c16 * 16),
                         s3 + row * NH + c16 * 8);
                }
            }
            asm volatile("cp.async.commit_group;" ::: "memory");
            asm volatile("cp.async.wait_group 1;" ::: "memory");
        } else {
            asm volatile("cp.async.wait_group 0;" ::: "memory");
        }
        __syncthreads();

        if (kb == 0) {
            #pragma unroll
            for (int i = 0; i < 16; i++) {
                acc[i][0] = 0.f; acc[i][1] = 0.f; acc[i][2] = 0.f; acc[i][3] = 0.f;
            }
        }

        // A fragments for this K-slab (reused across 16 n-tiles)
        uint32_t A[8][4];
        const int kbyte = kb * 256 + tg * 4;
        #pragma unroll
        for (int ks = 0; ks < 8; ks++) {
            int kof = kbyte + ks * 32;
            A[ks][0] = *(const uint32_t*)(h1r0 + kof);
            A[ks][1] = *(const uint32_t*)(h1r1 + kof);
            A[ks][2] = *(const uint32_t*)(h1r0 + kof + 16);
            A[ks][3] = *(const uint32_t*)(h1r1 + kof + 16);
        }
        const char* w2b = bp + W2_OFF + (c & 1) * W2_TILE + g * 272 + tg * 4;
        #pragma unroll
        for (int nt = 0; nt < 16; nt++) {
            const char* brow = w2b + nt * (8 * 272);
            #pragma unroll
            for (int ks = 0; ks < 8; ks++) {
                uint32_t b0 = *(const uint32_t*)(brow + ks * 32);
                uint32_t b1 = *(const uint32_t*)(brow + ks * 32 + 16);
                mma_bf16(acc[nt], A[ks], b0, b1);
            }
        }

        if (kb == 3) {
            // GEMM2(nb): A2 from GEMM1 accs (register-local), B from w3s.
            const char* w3b = bp + W3_OFF + g * 272 + tg * 4;
            #pragma unroll
            for (int j = 0; j < 8; j++) {
                int n0a = nb * 128 + j * 16 + tg * 2;
                int n0b = n0a + 8;
                float bA0 = b2s[n0a], bA1 = b2s[n0a + 1];
                float bB0 = b2s[n0b], bB1 = b2s[n0b + 1];
                uint32_t Af[4];
                Af[0] = pack_bf16x2(fmaxf(acc[2*j  ][0] + bA0, 0.f),
                                    fmaxf(acc[2*j  ][1] + bA1, 0.f));
                Af[1] = pack_bf16x2(fmaxf(acc[2*j  ][2] + bA0, 0.f),
                                    fmaxf(acc[2*j  ][3] + bA1, 0.f));
                Af[2] = pack_bf16x2(fmaxf(acc[2*j+1][0] + bB0, 0.f),
                                    fmaxf(acc[2*j+1][1] + bB1, 0.f));
                Af[3] = pack_bf16x2(fmaxf(acc[2*j+1][2] + bB0, 0.f),
                                    fmaxf(acc[2*j+1][3] + bB1, 0.f));
                #pragma unroll
                for (int nt3 = 0; nt3 < 8; nt3++) {
                    const char* brow = w3b + nt3 * (8 * 272) + j * 32;
                    uint32_t b0 = *(const uint32_t*)(brow);
                    uint32_t b1 = *(const uint32_t*)(brow + 16);
                    mma_bf16(lg[nt3], Af, b0, b1);
                }
            }
        }
        __syncthreads();
    }

    // ---- epilogue: softmax + pointed + valid head + sigmoid ----
    #pragma unroll
    for (int rr = 0; rr < 2; rr++) {
        const int r = m0 + g + rr * 8;
        const int o = rr * 2;
        float v[16];
        float mx = -1e30f;
        #pragma unroll
        for (int nt3 = 0; nt3 < 8; nt3++) {
            float x0 = lg[nt3][o]     + b3s[nt3 * 8 + tg * 2];
            float x1 = lg[nt3][o + 1] + b3s[nt3 * 8 + tg * 2 + 1];
            v[2 * nt3] = x0; v[2 * nt3 + 1] = x1;
            mx = fmaxf(mx, fmaxf(x0, x1));
        }
        mx = fmaxf(mx, __shfl_xor_sync(0xffffffffu, mx, 1));
        mx = fmaxf(mx, __shfl_xor_sync(0xffffffffu, mx, 2));

        const int bsel = r >> 6;
        const float* abr = ab_s + bsel * NBITS;
        float den = 0.f, num = 0.f;
        #pragma unroll
        for (int nt3 = 0; nt3 < 8; nt3++) {
            float e0 = expf(v[2 * nt3]     - mx);
            float e1 = expf(v[2 * nt3 + 1] - mx);
            den += e0 + e1;
            num += e0 * abr[nt3 * 8 + tg * 2] + e1 * abr[nt3 * 8 + tg * 2 + 1];
        }
        den += __shfl_xor_sync(0xffffffffu, den, 1);
        den += __shfl_xor_sync(0xffffffffu, den, 2);
        num += __shfl_xor_sync(0xffffffffu, num, 1);
        num += __shfl_xor_sync(0xffffffffu, num, 2);
        float pointed = num / den;

        const int R = r & 63;
        const float* vrow = v_w1 + R * NHV;
        const float* vsr  = vs_s + bsel * NHV;
        float acc2 = 0.f;
        #pragma unroll 8
        for (int jj = 0; jj < 64; jj++) {
            int j = jj * 4 + tg;
            float vh = fmaxf(vrow[j] + vsr[j], 0.f);
            acc2 = fmaf(vh, vw2s[j], acc2);
        }
        acc2 += __shfl_xor_sync(0xffffffffu, acc2, 1);
        acc2 += __shfl_xor_sync(0xffffffffu, acc2, 2);
        if (tg == 0) {
            float vlog = acc2 + v_b2[0];
            out[(2 * pair + bsel) * NBITS + R] =
                pointed * (1.f / (1.f + expf(-vlog)));
        }
    }
}

// ---------------------------------------------------------------------------
extern "C" void kernel_launch(void* const* d_in, const int* in_sizes, int n_in,
                              void* d_out, int out_size)
{
    const float* a_bits     = (const float*)d_in[0];
    const float* shift_bits = (const float*)d_in[1];
    const float* sd_w1 = (const float*)d_in[2];
    const float* sd_b1 = (const float*)d_in[3];
    const float* sd_w2 = (const float*)d_in[4];
    const float* sd_b2 = (const float*)d_in[5];
    const float* sd_w3 = (const float*)d_in[6];
    const float* sd_b3 = (const float*)d_in[7];
    const float* ix_w1 = (const float*)d_in[8];
    const float* ix_b1 = (const float*)d_in[9];
    const float* ix_w2 = (const float*)d_in[10];
    const float* ix_b2 = (const float*)d_in[11];
    const float* ix_w3 = (const float*)d_in[12];
    const float* ix_b3 = (const float*)d_in[13];
    const float* v_w1  = (const float*)d_in[14];
    const float* v_b1  = (const float*)d_in[15];
    const float* v_w2  = (const float*)d_in[16];
    const float* v_b2  = (const float*)d_in[17];
    float* out = (float*)d_out;

    cudaFuncSetAttribute(main_mma_kernel,
                         cudaFuncAttributeMaxDynamicSharedMemorySize, SM_TOTAL);

    prep_w2_kernel<<<1024, 256>>>(ix_w2);
    prep_w3_kernel<<<128, 256>>>(ix_w3);
    shift_net_kernel<<<NB / 8, 256>>>(shift_bits, sd_w1, sd_b1, sd_w2, sd_b2,
                                      sd_w3, sd_b3, ix_w1, v_w1);
    main_mma_kernel<<<NB / 2, 256, SM_TOTAL>>>(a_bits, ix_w1, ix_b1, ix_b2, ix_b3,
                                               v_w1, v_b1, v_w2, v_b2, out);
}